// round 2
// baseline (speedup 1.0000x reference)
#include <cuda_runtime.h>
#include <math.h>

// Problem constants
#define T_STEPS 512
#define BATCH   256
#define INF     1024
#define HIDDEN  1024
#define WROW    (INF + HIDDEN)
#define NCLS    512
#define BH      (BATCH * HIDDEN)      // 262144
#define TB      (T_STEPS * BATCH)     // 131072
#define NCTAS   128                   // persistent grid (<=148 SMs -> co-resident)

// Scratch (device globals: allocation-free rule)
__device__ float g_A[(size_t)T_STEPS * BH];  // x-projection + b_ih
__device__ float g_H[(size_t)T_STEPS * BH];  // all hidden states
__device__ unsigned g_cnt;                    // barrier arrival count (returns to 0)
__device__ unsigned g_gen;                    // barrier generation (monotonic across replays)

// ---------------------------------------------------------------------------
// Grid-wide barrier. Replay-safe: g_gen is monotonic; each launch reads its
// base generation before its first arrival (gen can't advance past a barrier
// until every CTA, including this one, arrives).
// ---------------------------------------------------------------------------
__device__ __forceinline__ void grid_bar(unsigned& lgen)
{
    __syncthreads();
    if (threadIdx.x == 0) {
        __threadfence();   // cumulative: publishes this CTA's (observed) writes
        if (atomicAdd(&g_cnt, 1u) == NCTAS - 1) {
            atomicExch(&g_cnt, 0u);
            __threadfence();
            atomicAdd(&g_gen, 1u);   // release
        } else {
            while (*(volatile unsigned*)&g_gen == lgen) { __nanosleep(64); }
            __threadfence();          // acquire
        }
        lgen++;
    }
    __syncthreads();
}

// ---------------------------------------------------------------------------
// Persistent recurrence kernel: for t in 0..511,
//   h_t = tanh(g_A[t] + h_{t-1} @ W_h^T),   W_h = W_ih[:, INF:]
// Grid: 128 CTAs x 256 threads; each CTA owns a 32(batch) x 64(hidden) tile.
// ---------------------------------------------------------------------------
__global__ void __launch_bounds__(256, 1)
rnn_recur(const float* __restrict__ W, const float* __restrict__ h0)
{
    __shared__ float As[32][34];   // [k][m], padded vs store conflicts
    __shared__ float Bs[32][66];   // [k][n], padded

    const int tid  = threadIdx.x;
    const int bm   = (blockIdx.x >> 4) * 32;   // batch tile base (8 tiles)
    const int bn   = (blockIdx.x & 15) * 64;   // hidden tile base (16 tiles)
    const int tcol = tid & 15;
    const int trow = tid >> 4;
    const int r0   = bm + trow * 2;
    const int c0   = bn + tcol * 4;
    const float* Wh = W + INF;                 // row stride WROW

    const int la_row = tid >> 3;               // 0..31 (A-tile gmem load map)
    const int la_kq  = tid & 7;                // 0..7

    unsigned lgen = *(volatile unsigned*)&g_gen;

    for (int t = 0; t < T_STEPS; t++) {
        const float* hprev = (t == 0) ? h0 : (g_H + (size_t)(t - 1) * BH);
        const size_t obase = (size_t)t * BH;

        // Prefetch the precomputed x-projection (+b_ih) for our output elems
        float4 pre0 = *(const float4*)(g_A + obase + (size_t)r0       * HIDDEN + c0);
        float4 pre1 = *(const float4*)(g_A + obase + (size_t)(r0 + 1) * HIDDEN + c0);

        float acc[2][4];
#pragma unroll
        for (int i = 0; i < 2; i++)
#pragma unroll
            for (int j = 0; j < 4; j++) acc[i][j] = 0.0f;

        for (int k0 = 0; k0 < HIDDEN; k0 += 32) {
            // A tile: 32 rows x 32 k  (256 float4s -> 1 per thread)
            {
                float4 v = *(const float4*)(hprev + (size_t)(bm + la_row) * HIDDEN
                                            + k0 + la_kq * 4);
                As[la_kq * 4 + 0][la_row] = v.x;
                As[la_kq * 4 + 1][la_row] = v.y;
                As[la_kq * 4 + 2][la_row] = v.z;
                As[la_kq * 4 + 3][la_row] = v.w;
            }
            // B tile: 64 rows x 32 k  (512 float4s -> 2 per thread)
#pragma unroll
            for (int it = 0; it < 2; it++) {
                int f4  = tid + it * 256;
                int row = f4 >> 3;
                int kq  = f4 & 7;
                float4 v = *(const float4*)(Wh + (size_t)(bn + row) * WROW
                                            + k0 + kq * 4);
                Bs[kq * 4 + 0][row] = v.x;
                Bs[kq * 4 + 1][row] = v.y;
                Bs[kq * 4 + 2][row] = v.z;
                Bs[kq * 4 + 3][row] = v.w;
            }
            __syncthreads();

#pragma unroll 16
            for (int k = 0; k < 32; k++) {
                float a0 = As[k][trow * 2 + 0];
                float a1 = As[k][trow * 2 + 1];
                float b0 = Bs[k][tcol * 4 + 0];
                float b1 = Bs[k][tcol * 4 + 1];
                float b2 = Bs[k][tcol * 4 + 2];
                float b3 = Bs[k][tcol * 4 + 3];
                acc[0][0] = fmaf(a0, b0, acc[0][0]);
                acc[0][1] = fmaf(a0, b1, acc[0][1]);
                acc[0][2] = fmaf(a0, b2, acc[0][2]);
                acc[0][3] = fmaf(a0, b3, acc[0][3]);
                acc[1][0] = fmaf(a1, b0, acc[1][0]);
                acc[1][1] = fmaf(a1, b1, acc[1][1]);
                acc[1][2] = fmaf(a1, b2, acc[1][2]);
                acc[1][3] = fmaf(a1, b3, acc[1][3]);
            }
            __syncthreads();
        }

        // Fused epilogue: h = tanh(acc + pre)
        float4 o0, o1;
        o0.x = tanhf(acc[0][0] + pre0.x);
        o0.y = tanhf(acc[0][1] + pre0.y);
        o0.z = tanhf(acc[0][2] + pre0.z);
        o0.w = tanhf(acc[0][3] + pre0.w);
        o1.x = tanhf(acc[1][0] + pre1.x);
        o1.y = tanhf(acc[1][1] + pre1.y);
        o1.z = tanhf(acc[1][2] + pre1.z);
        o1.w = tanhf(acc[1][3] + pre1.w);
        *(float4*)(g_H + obase + (size_t)r0       * HIDDEN + c0) = o0;
        *(float4*)(g_H + obase + (size_t)(r0 + 1) * HIDDEN + c0) = o1;

        grid_bar(lgen);   // publish h_t before anyone reads it at t+1
    }
}

// ---------------------------------------------------------------------------
// Generic NT SGEMM:  C[m,n] = sum_k A[m,k] * B[n,k]  (+ bias[n])
// ---------------------------------------------------------------------------
template<int BM, int BN, int BK, int TM, int TN>
__global__ void __launch_bounds__((BM / TM) * (BN / TN), 1)
sgemm_nt(const float* __restrict__ A, int lda,
         const float* __restrict__ B, int ldb,
         const float* __restrict__ bias,
         float* __restrict__ C, int ldc, int K)
{
    constexpr int THREADS = (BM / TM) * (BN / TN);
    __shared__ float As[BK][BM];
    __shared__ float Bs[BK][BN];

    const int bm  = blockIdx.y * BM;
    const int bn  = blockIdx.x * BN;
    const int tid = threadIdx.x;

    constexpr int KQ   = BK / 4;
    constexpr int A_IT = (BM * KQ) / THREADS;
    constexpr int B_IT = (BN * KQ) / THREADS;

    const int tcol = tid % (BN / TN);
    const int trow = tid / (BN / TN);

    float acc[TM][TN];
#pragma unroll
    for (int i = 0; i < TM; i++)
#pragma unroll
        for (int j = 0; j < TN; j++) acc[i][j] = 0.0f;

    for (int k0 = 0; k0 < K; k0 += BK) {
#pragma unroll
        for (int it = 0; it < A_IT; it++) {
            int f4  = tid + it * THREADS;
            int row = f4 / KQ;
            int kq  = f4 % KQ;
            float4 v = *(const float4*)(A + (long)(bm + row) * lda + k0 + kq * 4);
            As[kq * 4 + 0][row] = v.x;
            As[kq * 4 + 1][row] = v.y;
            As[kq * 4 + 2][row] = v.z;
            As[kq * 4 + 3][row] = v.w;
        }
#pragma unroll
        for (int it = 0; it < B_IT; it++) {
            int f4  = tid + it * THREADS;
            int row = f4 / KQ;
            int kq  = f4 % KQ;
            float4 v = *(const float4*)(B + (long)(bn + row) * ldb + k0 + kq * 4);
            Bs[kq * 4 + 0][row] = v.x;
            Bs[kq * 4 + 1][row] = v.y;
            Bs[kq * 4 + 2][row] = v.z;
            Bs[kq * 4 + 3][row] = v.w;
        }
        __syncthreads();

#pragma unroll
        for (int k = 0; k < BK; k++) {
            float a[TM], b[TN];
#pragma unroll
            for (int i = 0; i < TM; i += 4) {
                float4 v = *(const float4*)&As[k][trow * TM + i];
                a[i] = v.x; a[i + 1] = v.y; a[i + 2] = v.z; a[i + 3] = v.w;
            }
#pragma unroll
            for (int j = 0; j < TN; j += 4) {
                float4 v = *(const float4*)&Bs[k][tcol * TN + j];
                b[j] = v.x; b[j + 1] = v.y; b[j + 2] = v.z; b[j + 3] = v.w;
            }
#pragma unroll
            for (int i = 0; i < TM; i++)
#pragma unroll
                for (int j = 0; j < TN; j++)
                    acc[i][j] = fmaf(a[i], b[j], acc[i][j]);
        }
        __syncthreads();
    }

    float bv[TN];
#pragma unroll
    for (int j = 0; j < TN; j++) bv[j] = bias ? bias[bn + tcol * TN + j] : 0.0f;
#pragma unroll
    for (int i = 0; i < TM; i++) {
#pragma unroll
        for (int j = 0; j < TN; j += 4) {
            float4 v;
            v.x = acc[i][j + 0] + bv[j + 0];
            v.y = acc[i][j + 1] + bv[j + 1];
            v.z = acc[i][j + 2] + bv[j + 2];
            v.w = acc[i][j + 3] + bv[j + 3];
            *(float4*)(C + (long)(bm + trow * TM + i) * ldc + bn + tcol * TN + j) = v;
        }
    }
}

// ---------------------------------------------------------------------------
// In-place softmax over rows of 512 floats. 128 threads/block, float4 each.
// ---------------------------------------------------------------------------
__global__ void softmax512(float* __restrict__ O)
{
    __shared__ float red[4];
    long row = blockIdx.x;
    float4* p = (float4*)(O + row * (long)NCLS);
    float4 v = p[threadIdx.x];

    float m = fmaxf(fmaxf(v.x, v.y), fmaxf(v.z, v.w));
#pragma unroll
    for (int o = 16; o > 0; o >>= 1)
        m = fmaxf(m, __shfl_xor_sync(0xffffffffu, m, o));
    int warp = threadIdx.x >> 5;
    if ((threadIdx.x & 31) == 0) red[warp] = m;
    __syncthreads();
    m = fmaxf(fmaxf(red[0], red[1]), fmaxf(red[2], red[3]));

    float4 e;
    e.x = __expf(v.x - m);
    e.y = __expf(v.y - m);
    e.z = __expf(v.z - m);
    e.w = __expf(v.w - m);
    float s = e.x + e.y + e.z + e.w;
#pragma unroll
    for (int o = 16; o > 0; o >>= 1)
        s += __shfl_xor_sync(0xffffffffu, s, o);
    __syncthreads();
    if ((threadIdx.x & 31) == 0) red[warp] = s;
    __syncthreads();
    s = red[0] + red[1] + red[2] + red[3];

    float inv = 1.0f / s;
    e.x *= inv; e.y *= inv; e.z *= inv; e.w *= inv;
    p[threadIdx.x] = e;
}

// ---------------------------------------------------------------------------
// Launch: 5 graph nodes total (was 1028 -> caused the 2MB graph-pool flag).
// ---------------------------------------------------------------------------
extern "C" void kernel_launch(void* const* d_in, const int* in_sizes, int n_in,
                              void* d_out, int out_size)
{
    const float* x    = (const float*)d_in[0];   // [T, B, INF]
    const float* h0   = (const float*)d_in[1];   // [B, HIDDEN]
    const float* W_ih = (const float*)d_in[2];   // [HIDDEN, INF+HIDDEN]
    const float* b_ih = (const float*)d_in[3];   // [HIDDEN]
    const float* W_ho = (const float*)d_in[4];   // [NCLS, HIDDEN]
    const float* b_ho = (const float*)d_in[5];   // [NCLS]
    float*       out  = (float*)d_out;           // [T*B*NCLS] y, then [B*HIDDEN] h_last

    float *pA = nullptr, *pH = nullptr;
    cudaGetSymbolAddress((void**)&pA, g_A);
    cudaGetSymbolAddress((void**)&pH, g_H);

    // Phase 1: A = X @ W_x^T + b_ih   (W_x = W_ih[:, :INF])
    {
        dim3 grid(HIDDEN / 128, TB / 128, 1);
        sgemm_nt<128, 128, 16, 8, 8><<<grid, 256>>>(
            x, INF, W_ih, WROW, b_ih, pA, HIDDEN, INF);
    }

    // Phase 2: full recurrence in ONE persistent kernel (512 grid barriers)
    rnn_recur<<<NCTAS, 256>>>(W_ih, h0);

    // Phase 3: O = H @ W_ho^T + b_ho (into d_out), then in-place softmax
    {
        dim3 grid(NCLS / 128, TB / 128, 1);
        sgemm_nt<128, 128, 16, 8, 8><<<grid, 256>>>(
            pH, HIDDEN, W_ho, HIDDEN, b_ho, out, NCLS, HIDDEN);
        softmax512<<<TB, 128>>>(out);
    }

    // h_last = H[T-1]
    cudaMemcpyAsync(out + (long)TB * NCLS, pH + (long)(T_STEPS - 1) * BH,
                    (size_t)BH * sizeof(float), cudaMemcpyDeviceToDevice);
}

// round 4
// speedup vs baseline: 2.4837x; 2.4837x over previous
#include <cuda_runtime.h>
#include <cuda_bf16.h>
#include <math.h>
#include <stdint.h>

// ---------------------------------------------------------------------------
// Problem constants
// ---------------------------------------------------------------------------
#define T_STEPS 512
#define BATCH   256
#define INF     1024
#define HIDDEN  1024
#define WROW    (INF + HIDDEN)
#define NCLS    512
#define BH      (BATCH * HIDDEN)      // 262144
#define TB      (T_STEPS * BATCH)     // 131072
#define NCTAS   128                   // persistent recurrence grid

// ---------------------------------------------------------------------------
// Device-global scratch (allocation-free rule)
// ---------------------------------------------------------------------------
__device__ float g_A[(size_t)T_STEPS * BH];           // x-projection + b_ih (fp32)
__device__ float g_Hlast[BH];                          // final hidden state (fp32)
__device__ __nv_bfloat16 g_Xh[(size_t)TB * INF];      // X split hi
__device__ __nv_bfloat16 g_Xl[(size_t)TB * INF];      // X split lo
__device__ __nv_bfloat16 g_Hh[(size_t)T_STEPS * BH];  // H split hi
__device__ __nv_bfloat16 g_Hl[(size_t)T_STEPS * BH];  // H split lo
__device__ __nv_bfloat16 g_Wih_h[HIDDEN * WROW];      // W_ih hi (full, row stride WROW)
__device__ __nv_bfloat16 g_Wih_l[HIDDEN * WROW];
__device__ __nv_bfloat16 g_Who_h[NCLS * HIDDEN];      // W_ho hi
__device__ __nv_bfloat16 g_Who_l[NCLS * HIDDEN];
__device__ __nv_bfloat16 g_h0h[BH];                   // h0 split hi
__device__ __nv_bfloat16 g_h0l[BH];
__device__ unsigned g_cnt;                             // grid barrier count
__device__ unsigned g_gen;                             // grid barrier generation

// ---------------------------------------------------------------------------
// Portable PTX helpers (sm_80+ features only; NO sm_103a-only instructions)
// ---------------------------------------------------------------------------
__device__ __forceinline__ uint32_t smem_to_u32(const void* p) {
    uint32_t a;
    asm("{ .reg .u64 t; cvta.to.shared.u64 t, %1; cvt.u32.u64 %0, t; }"
        : "=r"(a) : "l"(p));
    return a;
}

__device__ __forceinline__ void cp16(uint32_t dst, const void* src) {
    asm volatile("cp.async.cg.shared.global [%0], [%1], 16;"
                 :: "r"(dst), "l"(__cvta_generic_to_global(src)));
}
#define CP_COMMIT()  asm volatile("cp.async.commit_group;" ::: "memory")
#define CP_WAIT(n)   asm volatile("cp.async.wait_group %0;" :: "n"(n) : "memory")

#define LDSM4(r0, r1, r2, r3, addr) \
    asm volatile("ldmatrix.sync.aligned.m8n8.x4.shared.b16 {%0,%1,%2,%3}, [%4];" \
                 : "=r"(r0), "=r"(r1), "=r"(r2), "=r"(r3) : "r"(addr))
#define LDSM2(r0, r1, addr) \
    asm volatile("ldmatrix.sync.aligned.m8n8.x2.shared.b16 {%0,%1}, [%2];" \
                 : "=r"(r0), "=r"(r1) : "r"(addr))

// D[16x8] += A[16x16] * B[16x8]^(col)  -- bf16 in, fp32 accum
__device__ __forceinline__ void mma_bf16(float* c, const uint32_t* a, const uint32_t* b) {
    asm volatile(
        "mma.sync.aligned.m16n8k16.row.col.f32.bf16.bf16.f32 "
        "{%0,%1,%2,%3}, {%4,%5,%6,%7}, {%8,%9}, {%0,%1,%2,%3};"
        : "+f"(c[0]), "+f"(c[1]), "+f"(c[2]), "+f"(c[3])
        : "r"(a[0]), "r"(a[1]), "r"(a[2]), "r"(a[3]), "r"(b[0]), "r"(b[1]));
}

// ---------------------------------------------------------------------------
// fp32 -> (hi, lo) bf16 split
// ---------------------------------------------------------------------------
__device__ __forceinline__ void split1(float v, __nv_bfloat16& h, __nv_bfloat16& l) {
    h = __float2bfloat16(v);
    l = __float2bfloat16(v - __bfloat162float(h));
}

__global__ void split_mat(const float* __restrict__ src, long lda, long rows, long cols,
                          __nv_bfloat16* __restrict__ hi, __nv_bfloat16* __restrict__ lo)
{
    long n4 = rows * cols / 4;
    for (long i = blockIdx.x * (long)blockDim.x + threadIdx.x; i < n4;
         i += (long)gridDim.x * blockDim.x) {
        long e = i * 4;
        long r = e / cols, c = e % cols;
        float4 v = *(const float4*)(src + r * lda + c);
        __nv_bfloat16 h0, h1, h2, h3, l0, l1, l2, l3;
        split1(v.x, h0, l0); split1(v.y, h1, l1);
        split1(v.z, h2, l2); split1(v.w, h3, l3);
        __nv_bfloat162 t;
        t.x = h0; t.y = h1; *(__nv_bfloat162*)(hi + e)     = t;
        t.x = h2; t.y = h3; *(__nv_bfloat162*)(hi + e + 2) = t;
        t.x = l0; t.y = l1; *(__nv_bfloat162*)(lo + e)     = t;
        t.x = l2; t.y = l3; *(__nv_bfloat162*)(lo + e + 2) = t;
    }
}

// ---------------------------------------------------------------------------
// mma.sync bf16x3 GEMM:  C[m,n] = sum_k (Ah+Al)[m,k]*(Bh+Bl)[n,k] + bias[n]
// (drops Al*Bl).  CTA tile 128x128, BK=32, 8 warps (4M x 2N), 2-stage cp.async.
// smem rows padded to 80B (64B data + 16B) -> conflict-free ldmatrix.
// ---------------------------------------------------------------------------
#define ROWB   80
#define G_MAT  (128 * ROWB)          // 10240 bytes per matrix tile
#define G_STG  (4 * G_MAT)           // Ah, Al, Bh, Bl = 40960
#define G_SMEM (2 * G_STG)           // 81920

__global__ void __launch_bounds__(256, 1)
gemm_mma_x3(const __nv_bfloat16* __restrict__ Ah, const __nv_bfloat16* __restrict__ Al, long lda,
            const __nv_bfloat16* __restrict__ Bh, const __nv_bfloat16* __restrict__ Bl, long ldb,
            const float* __restrict__ bias, float* __restrict__ C, long ldc, int K)
{
    extern __shared__ char smem[];
    const uint32_t sb = smem_to_u32(smem);
    const int tid = threadIdx.x, lane = tid & 31, wid = tid >> 5;
    const int wm = wid & 3, wn = wid >> 2;           // 4 x 2 warp grid
    const long bm = (long)blockIdx.y * 128;
    const long bn = (long)blockIdx.x * 128;

    float c[2][8][4];
#pragma unroll
    for (int m = 0; m < 2; m++)
#pragma unroll
        for (int n = 0; n < 8; n++)
#pragma unroll
            for (int j = 0; j < 4; j++) c[m][n][j] = 0.0f;

    // ldmatrix per-lane offsets
    const uint32_t a_rb = (uint32_t)(lane & 15) * ROWB + (uint32_t)(lane >> 4) * 16;
    const uint32_t b_rb = (uint32_t)(lane & 7) * ROWB + (uint32_t)((lane >> 3) & 1) * 16;

    auto load_chunk = [&](int kc, int stage) {
        uint32_t base = sb + stage * G_STG;
#pragma unroll
        for (int it = 0; it < 2; it++) {
            int u = tid + it * 256;                   // 512 units of 16B per matrix
            int row = u >> 2, seg = u & 3;
            uint32_t so = row * ROWB + seg * 16;
            long ga = (bm + row) * lda + kc + seg * 8;
            long gb = (bn + row) * ldb + kc + seg * 8;
            cp16(base + so,             Ah + ga);
            cp16(base + G_MAT + so,     Al + ga);
            cp16(base + 2 * G_MAT + so, Bh + gb);
            cp16(base + 3 * G_MAT + so, Bl + gb);
        }
    };

    const int nchunk = K >> 5;
    load_chunk(0, 0);
    CP_COMMIT();

    for (int ch = 0; ch < nchunk; ch++) {
        if (ch + 1 < nchunk) {
            load_chunk((ch + 1) << 5, (ch + 1) & 1);
            CP_COMMIT();
            CP_WAIT(1);
        } else {
            CP_WAIT(0);
        }
        __syncthreads();

        const uint32_t base = sb + (ch & 1) * G_STG;
#pragma unroll
        for (int k16 = 0; k16 < 2; k16++) {
            const uint32_t kb = k16 * 32;
            uint32_t ah[2][4], al[2][4], bh[8][2], bl[8][2];
#pragma unroll
            for (int m = 0; m < 2; m++) {
                uint32_t ra = base + (uint32_t)(wm * 32 + m * 16) * ROWB + kb + a_rb;
                LDSM4(ah[m][0], ah[m][1], ah[m][2], ah[m][3], ra);
                LDSM4(al[m][0], al[m][1], al[m][2], al[m][3], ra + G_MAT);
            }
#pragma unroll
            for (int n = 0; n < 8; n++) {
                uint32_t rb = base + 2 * G_MAT + (uint32_t)(wn * 64 + n * 8) * ROWB + kb + b_rb;
                LDSM2(bh[n][0], bh[n][1], rb);
                LDSM2(bl[n][0], bl[n][1], rb + G_MAT);
            }
#pragma unroll
            for (int m = 0; m < 2; m++)
#pragma unroll
                for (int n = 0; n < 8; n++) {
                    mma_bf16(c[m][n], ah[m], bh[n]);
                    mma_bf16(c[m][n], al[m], bh[n]);
                    mma_bf16(c[m][n], ah[m], bl[n]);
                }
        }
        __syncthreads();
    }

    // Epilogue: add bias, fp32 stores
#pragma unroll
    for (int m = 0; m < 2; m++) {
        long r0 = bm + wm * 32 + m * 16 + (lane >> 2);
        long r1 = r0 + 8;
#pragma unroll
        for (int n = 0; n < 8; n++) {
            long col = bn + wn * 64 + n * 8 + (lane & 3) * 2;
            float bx = bias[col], by = bias[col + 1];
            float2 v0 = { c[m][n][0] + bx, c[m][n][1] + by };
            float2 v1 = { c[m][n][2] + bx, c[m][n][3] + by };
            *(float2*)(C + r0 * ldc + col) = v0;
            *(float2*)(C + r1 * ldc + col) = v1;
        }
    }
}

// ---------------------------------------------------------------------------
// Grid-wide barrier (replay-safe, monotonic generation)
// ---------------------------------------------------------------------------
__device__ __forceinline__ void grid_bar(unsigned& lgen)
{
    __syncthreads();
    if (threadIdx.x == 0) {
        __threadfence();
        if (atomicAdd(&g_cnt, 1u) == NCTAS - 1) {
            atomicExch(&g_cnt, 0u);
            __threadfence();
            atomicAdd(&g_gen, 1u);
        } else {
            while (*(volatile unsigned*)&g_gen == lgen) { __nanosleep(64); }
            __threadfence();
        }
        lgen++;
    }
    __syncthreads();
}

// ---------------------------------------------------------------------------
// Persistent recurrence on mma.sync (bf16x4 split for compounding safety):
//   h_t = tanh(g_A[t] + h_{t-1} @ W_h^T)
// 128 CTAs x 256 thr; CTA tile 32(M) x 64(N); warps 2(M) x 4(N), 16x16 each.
// Emits h_t as bf16 hi/lo; fp32 only at t = T-1.
// ---------------------------------------------------------------------------
#define R_A    (32 * ROWB)                 // 2560
#define R_B    (64 * ROWB)                 // 5120
#define R_STG  (2 * R_A + 2 * R_B)         // 15360
// layout per stage: Ah:0  Al:R_A  Bh:2*R_A  Bl:2*R_A+R_B

__global__ void __launch_bounds__(256, 1)
rnn_recur()
{
    __shared__ char rs[2 * R_STG];         // 30720
    const uint32_t sb = smem_to_u32(rs);
    const int tid = threadIdx.x, lane = tid & 31, wid = tid >> 5;
    const int wm = wid & 1, wn = wid >> 1;       // 2 x 4 warp grid
    const int bm = (blockIdx.x >> 4) * 32;       // 8 M-tiles
    const int bn = (blockIdx.x & 15) * 64;       // 16 N-tiles

    const uint32_t a_rb = (uint32_t)(lane & 15) * ROWB + (uint32_t)(lane >> 4) * 16;
    const uint32_t b_rb = (uint32_t)(lane & 7) * ROWB + (uint32_t)((lane >> 3) & 1) * 16;

    // B (weight) load map: 256 units of 16B (64 rows x 4 segs)
    const int wrow = tid >> 2, wseg = tid & 3;
    // A load map: 128 units (32 rows x 4 segs), threads 0-127
    const int arow = tid >> 2, aseg = tid & 3;   // valid when tid < 128

    unsigned lgen = *(volatile unsigned*)&g_gen;

    for (int t = 0; t < T_STEPS; t++) {
        const __nv_bfloat16* hh = (t == 0) ? g_h0h : (g_Hh + (size_t)(t - 1) * BH);
        const __nv_bfloat16* hl = (t == 0) ? g_h0l : (g_Hl + (size_t)(t - 1) * BH);

        float c[2][4];
#pragma unroll
        for (int n = 0; n < 2; n++)
#pragma unroll
            for (int j = 0; j < 4; j++) c[n][j] = 0.0f;

        auto load_chunk = [&](int kc, int stage) {
            uint32_t base = sb + stage * R_STG;
            if (tid < 128) {
                uint32_t so = arow * ROWB + aseg * 16;
                size_t g = (size_t)(bm + arow) * HIDDEN + kc + aseg * 8;
                cp16(base + so,       hh + g);
                cp16(base + R_A + so, hl + g);
            }
            {
                uint32_t so = wrow * ROWB + wseg * 16;
                size_t g = (size_t)(bn + wrow) * WROW + INF + kc + wseg * 8;
                cp16(base + 2 * R_A + so,       g_Wih_h + g);
                cp16(base + 2 * R_A + R_B + so, g_Wih_l + g);
            }
        };

        load_chunk(0, 0);
        CP_COMMIT();

        for (int ch = 0; ch < HIDDEN / 32; ch++) {
            if (ch + 1 < HIDDEN / 32) {
                load_chunk((ch + 1) << 5, (ch + 1) & 1);
                CP_COMMIT();
                CP_WAIT(1);
            } else {
                CP_WAIT(0);
            }
            __syncthreads();

            const uint32_t base = sb + (ch & 1) * R_STG;
#pragma unroll
            for (int k16 = 0; k16 < 2; k16++) {
                const uint32_t kb = k16 * 32;
                uint32_t ah[4], al[4], bh[2][2], bl[2][2];
                uint32_t ra = base + (uint32_t)(wm * 16) * ROWB + kb + a_rb;
                LDSM4(ah[0], ah[1], ah[2], ah[3], ra);
                LDSM4(al[0], al[1], al[2], al[3], ra + R_A);
#pragma unroll
                for (int n = 0; n < 2; n++) {
                    uint32_t rb = base + 2 * R_A + (uint32_t)(wn * 16 + n * 8) * ROWB + kb + b_rb;
                    LDSM2(bh[n][0], bh[n][1], rb);
                    LDSM2(bl[n][0], bl[n][1], rb + R_B);
                }
#pragma unroll
                for (int n = 0; n < 2; n++) {
                    mma_bf16(c[n], ah, bh[n]);
                    mma_bf16(c[n], al, bh[n]);
                    mma_bf16(c[n], ah, bl[n]);
                    mma_bf16(c[n], al, bl[n]);
                }
            }
            __syncthreads();
        }

        // Epilogue: tanh(acc + pre), split to bf16 hi/lo
        {
            const size_t ob = (size_t)t * BH;
            int r0 = bm + wm * 16 + (lane >> 2);
            int r1 = r0 + 8;
#pragma unroll
            for (int n = 0; n < 2; n++) {
                int col = bn + wn * 16 + n * 8 + (lane & 3) * 2;
                float2 p0 = *(const float2*)(g_A + ob + (size_t)r0 * HIDDEN + col);
                float2 p1 = *(const float2*)(g_A + ob + (size_t)r1 * HIDDEN + col);
                float h00 = tanhf(c[n][0] + p0.x);
                float h01 = tanhf(c[n][1] + p0.y);
                float h10 = tanhf(c[n][2] + p1.x);
                float h11 = tanhf(c[n][3] + p1.y);

                __nv_bfloat16 hb, lb;
                __nv_bfloat162 th, tl;
                split1(h00, hb, lb); th.x = hb; tl.x = lb;
                split1(h01, hb, lb); th.y = hb; tl.y = lb;
                *(__nv_bfloat162*)(g_Hh + ob + (size_t)r0 * HIDDEN + col) = th;
                *(__nv_bfloat162*)(g_Hl + ob + (size_t)r0 * HIDDEN + col) = tl;
                split1(h10, hb, lb); th.x = hb; tl.x = lb;
                split1(h11, hb, lb); th.y = hb; tl.y = lb;
                *(__nv_bfloat162*)(g_Hh + ob + (size_t)r1 * HIDDEN + col) = th;
                *(__nv_bfloat162*)(g_Hl + ob + (size_t)r1 * HIDDEN + col) = tl;

                if (t == T_STEPS - 1) {
                    float2 f0 = { h00, h01 }, f1 = { h10, h11 };
                    *(float2*)(g_Hlast + (size_t)r0 * HIDDEN + col) = f0;
                    *(float2*)(g_Hlast + (size_t)r1 * HIDDEN + col) = f1;
                }
            }
        }

        grid_bar(lgen);
    }
}

// ---------------------------------------------------------------------------
// In-place softmax over rows of 512 floats
// ---------------------------------------------------------------------------
__global__ void softmax512(float* __restrict__ O)
{
    __shared__ float red[4];
    long row = blockIdx.x;
    float4* p = (float4*)(O + row * (long)NCLS);
    float4 v = p[threadIdx.x];

    float m = fmaxf(fmaxf(v.x, v.y), fmaxf(v.z, v.w));
#pragma unroll
    for (int o = 16; o > 0; o >>= 1)
        m = fmaxf(m, __shfl_xor_sync(0xffffffffu, m, o));
    int warp = threadIdx.x >> 5;
    if ((threadIdx.x & 31) == 0) red[warp] = m;
    __syncthreads();
    m = fmaxf(fmaxf(red[0], red[1]), fmaxf(red[2], red[3]));

    float4 e;
    e.x = __expf(v.x - m);
    e.y = __expf(v.y - m);
    e.z = __expf(v.z - m);
    e.w = __expf(v.w - m);
    float s = e.x + e.y + e.z + e.w;
#pragma unroll
    for (int o = 16; o > 0; o >>= 1)
        s += __shfl_xor_sync(0xffffffffu, s, o);
    __syncthreads();
    if ((threadIdx.x & 31) == 0) red[warp] = s;
    __syncthreads();
    s = red[0] + red[1] + red[2] + red[3];

    float inv = 1.0f / s;
    e.x *= inv; e.y *= inv; e.z *= inv; e.w *= inv;
    p[threadIdx.x] = e;
}

// ---------------------------------------------------------------------------
// Launch (9 graph nodes)
// ---------------------------------------------------------------------------
extern "C" void kernel_launch(void* const* d_in, const int* in_sizes, int n_in,
                              void* d_out, int out_size)
{
    const float* x    = (const float*)d_in[0];
    const float* h0   = (const float*)d_in[1];
    const float* W_ih = (const float*)d_in[2];
    const float* b_ih = (const float*)d_in[3];
    const float* W_ho = (const float*)d_in[4];
    const float* b_ho = (const float*)d_in[5];
    float*       out  = (float*)d_out;

    float *pA, *pHlast;
    __nv_bfloat16 *pXh, *pXl, *pHh, *pHl, *pWih_h, *pWih_l, *pWoh, *pWol, *ph0h, *ph0l;
    cudaGetSymbolAddress((void**)&pA,     g_A);
    cudaGetSymbolAddress((void**)&pHlast, g_Hlast);
    cudaGetSymbolAddress((void**)&pXh,    g_Xh);
    cudaGetSymbolAddress((void**)&pXl,    g_Xl);
    cudaGetSymbolAddress((void**)&pHh,    g_Hh);
    cudaGetSymbolAddress((void**)&pHl,    g_Hl);
    cudaGetSymbolAddress((void**)&pWih_h, g_Wih_h);
    cudaGetSymbolAddress((void**)&pWih_l, g_Wih_l);
    cudaGetSymbolAddress((void**)&pWoh,   g_Who_h);
    cudaGetSymbolAddress((void**)&pWol,   g_Who_l);
    cudaGetSymbolAddress((void**)&ph0h,   g_h0h);
    cudaGetSymbolAddress((void**)&ph0l,   g_h0l);

    cudaFuncSetAttribute(gemm_mma_x3,
                         cudaFuncAttributeMaxDynamicSharedMemorySize, G_SMEM);

    // Splits: X, W_ih (full), W_ho, h0
    split_mat<<<4096, 256>>>(x,    INF,    TB,     INF,    pXh,    pXl);
    split_mat<<<512,  256>>>(W_ih, WROW,   HIDDEN, WROW,   pWih_h, pWih_l);
    split_mat<<<256,  256>>>(W_ho, HIDDEN, NCLS,   HIDDEN, pWoh,   pWol);
    split_mat<<<128,  256>>>(h0,   HIDDEN, BATCH,  HIDDEN, ph0h,   ph0l);

    // Phase 1: g_A = X @ Wx^T + b_ih   (Wx = W_ih[:, :INF], row stride WROW)
    {
        dim3 grid(HIDDEN / 128, TB / 128);   // (8, 1024)
        gemm_mma_x3<<<grid, 256, G_SMEM>>>(pXh, pXl, INF,
                                           pWih_h, pWih_l, WROW,
                                           b_ih, pA, HIDDEN, INF);
    }

    // Phase 2: persistent recurrence (mma.sync bf16x4)
    rnn_recur<<<NCTAS, 256>>>();

    // Phase 3: out = H @ W_ho^T + b_ho, then in-place softmax
    {
        dim3 grid(NCLS / 128, TB / 128);     // (4, 1024)
        gemm_mma_x3<<<grid, 256, G_SMEM>>>(pHh, pHl, HIDDEN,
                                           pWoh, pWol, HIDDEN,
                                           b_ho, out, NCLS, HIDDEN);
        softmax512<<<TB, 128>>>(out);
    }

    // h_last
    cudaMemcpyAsync(out + (long)TB * NCLS, pHlast,
                    (size_t)BH * sizeof(float), cudaMemcpyDeviceToDevice);
}

// round 5
// speedup vs baseline: 2.7904x; 1.1235x over previous
#include <cuda_runtime.h>
#include <cuda_bf16.h>
#include <math.h>
#include <stdint.h>

// ---------------------------------------------------------------------------
// Problem constants
// ---------------------------------------------------------------------------
#define T_STEPS 512
#define BATCH   256
#define INF     1024
#define HIDDEN  1024
#define WROW    (INF + HIDDEN)
#define NCLS    512
#define BH      (BATCH * HIDDEN)      // 262144
#define TB      (T_STEPS * BATCH)     // 131072
#define NCTAS   128                   // persistent recurrence grid

// ---------------------------------------------------------------------------
// Device-global scratch (allocation-free rule)
// ---------------------------------------------------------------------------
__device__ float g_A[(size_t)T_STEPS * BH];           // x-projection + b_ih (fp32)
__device__ float g_Hlast[BH];                          // final hidden state (fp32)
__device__ __nv_bfloat16 g_Xh[(size_t)TB * INF];      // X split hi
__device__ __nv_bfloat16 g_Xl[(size_t)TB * INF];      // X split lo
__device__ __nv_bfloat16 g_Hh[(size_t)T_STEPS * BH];  // H split hi
__device__ __nv_bfloat16 g_Hl[(size_t)T_STEPS * BH];  // H split lo
__device__ __nv_bfloat16 g_Wih_h[HIDDEN * WROW];      // W_ih hi (full, row stride WROW)
__device__ __nv_bfloat16 g_Wih_l[HIDDEN * WROW];
__device__ __nv_bfloat16 g_Who_h[NCLS * HIDDEN];      // W_ho hi
__device__ __nv_bfloat16 g_Who_l[NCLS * HIDDEN];
__device__ __nv_bfloat16 g_h0h[BH];                   // h0 split hi
__device__ __nv_bfloat16 g_h0l[BH];
__device__ unsigned g_cnt;                             // grid barrier count
__device__ unsigned g_gen;                             // grid barrier generation

// ---------------------------------------------------------------------------
// Portable PTX helpers (sm_80+ features only; NO sm_103a-only instructions)
// ---------------------------------------------------------------------------
__device__ __forceinline__ uint32_t smem_to_u32(const void* p) {
    uint32_t a;
    asm("{ .reg .u64 t; cvta.to.shared.u64 t, %1; cvt.u32.u64 %0, t; }"
        : "=r"(a) : "l"(p));
    return a;
}

__device__ __forceinline__ void cp16(uint32_t dst, const void* src) {
    asm volatile("cp.async.cg.shared.global [%0], [%1], 16;"
                 :: "r"(dst), "l"(__cvta_generic_to_global(src)));
}
#define CP_COMMIT()  asm volatile("cp.async.commit_group;" ::: "memory")
#define CP_WAIT(n)   asm volatile("cp.async.wait_group %0;" :: "n"(n) : "memory")

#define LDSM4(r0, r1, r2, r3, addr) \
    asm volatile("ldmatrix.sync.aligned.m8n8.x4.shared.b16 {%0,%1,%2,%3}, [%4];" \
                 : "=r"(r0), "=r"(r1), "=r"(r2), "=r"(r3) : "r"(addr))
#define LDSM2(r0, r1, addr) \
    asm volatile("ldmatrix.sync.aligned.m8n8.x2.shared.b16 {%0,%1}, [%2];" \
                 : "=r"(r0), "=r"(r1) : "r"(addr))

// D[16x8] += A[16x16] * B[16x8]^(col)  -- bf16 in, fp32 accum
__device__ __forceinline__ void mma_bf16(float* c, const uint32_t* a, const uint32_t* b) {
    asm volatile(
        "mma.sync.aligned.m16n8k16.row.col.f32.bf16.bf16.f32 "
        "{%0,%1,%2,%3}, {%4,%5,%6,%7}, {%8,%9}, {%0,%1,%2,%3};"
        : "+f"(c[0]), "+f"(c[1]), "+f"(c[2]), "+f"(c[3])
        : "r"(a[0]), "r"(a[1]), "r"(a[2]), "r"(a[3]), "r"(b[0]), "r"(b[1]));
}

// ---------------------------------------------------------------------------
// fp32 -> (hi, lo) bf16 split
// ---------------------------------------------------------------------------
__device__ __forceinline__ void split1(float v, __nv_bfloat16& h, __nv_bfloat16& l) {
    h = __float2bfloat16(v);
    l = __float2bfloat16(v - __bfloat162float(h));
}

__global__ void split_mat(const float* __restrict__ src, long lda, long rows, long cols,
                          __nv_bfloat16* __restrict__ hi, __nv_bfloat16* __restrict__ lo)
{
    long n4 = rows * cols / 4;
    for (long i = blockIdx.x * (long)blockDim.x + threadIdx.x; i < n4;
         i += (long)gridDim.x * blockDim.x) {
        long e = i * 4;
        long r = e / cols, c = e % cols;
        float4 v = *(const float4*)(src + r * lda + c);
        __nv_bfloat16 h0, h1, h2, h3, l0, l1, l2, l3;
        split1(v.x, h0, l0); split1(v.y, h1, l1);
        split1(v.z, h2, l2); split1(v.w, h3, l3);
        __nv_bfloat162 t;
        t.x = h0; t.y = h1; *(__nv_bfloat162*)(hi + e)     = t;
        t.x = h2; t.y = h3; *(__nv_bfloat162*)(hi + e + 2) = t;
        t.x = l0; t.y = l1; *(__nv_bfloat162*)(lo + e)     = t;
        t.x = l2; t.y = l3; *(__nv_bfloat162*)(lo + e + 2) = t;
    }
}

// ---------------------------------------------------------------------------
// mma.sync bf16x3 GEMM:  C[m,n] = sum_k (Ah+Al)[m,k]*(Bh+Bl)[n,k] + bias[n]
// (drops Al*Bl).  CTA tile 128x128, BK=32, 8 warps (4M x 2N), 2-stage cp.async.
// smem rows padded to 80B (64B data + 16B) -> conflict-free ldmatrix.
// ---------------------------------------------------------------------------
#define ROWB   80
#define G_MAT  (128 * ROWB)          // 10240 bytes per matrix tile
#define G_STG  (4 * G_MAT)           // Ah, Al, Bh, Bl = 40960
#define G_SMEM (2 * G_STG)           // 81920

__global__ void __launch_bounds__(256, 1)
gemm_mma_x3(const __nv_bfloat16* __restrict__ Ah, const __nv_bfloat16* __restrict__ Al, long lda,
            const __nv_bfloat16* __restrict__ Bh, const __nv_bfloat16* __restrict__ Bl, long ldb,
            const float* __restrict__ bias, float* __restrict__ C, long ldc, int K)
{
    extern __shared__ char smem[];
    const uint32_t sb = smem_to_u32(smem);
    const int tid = threadIdx.x, lane = tid & 31, wid = tid >> 5;
    const int wm = wid & 3, wn = wid >> 2;           // 4 x 2 warp grid
    const long bm = (long)blockIdx.y * 128;
    const long bn = (long)blockIdx.x * 128;

    float c[2][8][4];
#pragma unroll
    for (int m = 0; m < 2; m++)
#pragma unroll
        for (int n = 0; n < 8; n++)
#pragma unroll
            for (int j = 0; j < 4; j++) c[m][n][j] = 0.0f;

    const uint32_t a_rb = (uint32_t)(lane & 15) * ROWB + (uint32_t)(lane >> 4) * 16;
    const uint32_t b_rb = (uint32_t)(lane & 7) * ROWB + (uint32_t)((lane >> 3) & 1) * 16;

    auto load_chunk = [&](int kc, int stage) {
        uint32_t base = sb + stage * G_STG;
#pragma unroll
        for (int it = 0; it < 2; it++) {
            int u = tid + it * 256;
            int row = u >> 2, seg = u & 3;
            uint32_t so = row * ROWB + seg * 16;
            long ga = (bm + row) * lda + kc + seg * 8;
            long gb = (bn + row) * ldb + kc + seg * 8;
            cp16(base + so,             Ah + ga);
            cp16(base + G_MAT + so,     Al + ga);
            cp16(base + 2 * G_MAT + so, Bh + gb);
            cp16(base + 3 * G_MAT + so, Bl + gb);
        }
    };

    const int nchunk = K >> 5;
    load_chunk(0, 0);
    CP_COMMIT();

    for (int ch = 0; ch < nchunk; ch++) {
        if (ch + 1 < nchunk) {
            load_chunk((ch + 1) << 5, (ch + 1) & 1);
            CP_COMMIT();
            CP_WAIT(1);
        } else {
            CP_WAIT(0);
        }
        __syncthreads();

        const uint32_t base = sb + (ch & 1) * G_STG;
#pragma unroll
        for (int k16 = 0; k16 < 2; k16++) {
            const uint32_t kb = k16 * 32;
            uint32_t ah[2][4], al[2][4], bh[8][2], bl[8][2];
#pragma unroll
            for (int m = 0; m < 2; m++) {
                uint32_t ra = base + (uint32_t)(wm * 32 + m * 16) * ROWB + kb + a_rb;
                LDSM4(ah[m][0], ah[m][1], ah[m][2], ah[m][3], ra);
                LDSM4(al[m][0], al[m][1], al[m][2], al[m][3], ra + G_MAT);
            }
#pragma unroll
            for (int n = 0; n < 8; n++) {
                uint32_t rb = base + 2 * G_MAT + (uint32_t)(wn * 64 + n * 8) * ROWB + kb + b_rb;
                LDSM2(bh[n][0], bh[n][1], rb);
                LDSM2(bl[n][0], bl[n][1], rb + G_MAT);
            }
#pragma unroll
            for (int m = 0; m < 2; m++)
#pragma unroll
                for (int n = 0; n < 8; n++) {
                    mma_bf16(c[m][n], ah[m], bh[n]);
                    mma_bf16(c[m][n], al[m], bh[n]);
                    mma_bf16(c[m][n], ah[m], bl[n]);
                }
        }
        __syncthreads();
    }

#pragma unroll
    for (int m = 0; m < 2; m++) {
        long r0 = bm + wm * 32 + m * 16 + (lane >> 2);
        long r1 = r0 + 8;
#pragma unroll
        for (int n = 0; n < 8; n++) {
            long col = bn + wn * 64 + n * 8 + (lane & 3) * 2;
            float bx = bias[col], by = bias[col + 1];
            float2 v0 = { c[m][n][0] + bx, c[m][n][1] + by };
            float2 v1 = { c[m][n][2] + bx, c[m][n][3] + by };
            *(float2*)(C + r0 * ldc + col) = v0;
            *(float2*)(C + r1 * ldc + col) = v1;
        }
    }
}

// ---------------------------------------------------------------------------
// Grid-wide barrier (replay-safe, monotonic generation)
// ---------------------------------------------------------------------------
__device__ __forceinline__ void grid_bar(unsigned& lgen)
{
    __syncthreads();
    if (threadIdx.x == 0) {
        __threadfence();
        if (atomicAdd(&g_cnt, 1u) == NCTAS - 1) {
            atomicExch(&g_cnt, 0u);
            __threadfence();
            atomicAdd(&g_gen, 1u);
        } else {
            while (*(volatile unsigned*)&g_gen == lgen) { __nanosleep(32); }
            __threadfence();
        }
        lgen++;
    }
    __syncthreads();
}

// ---------------------------------------------------------------------------
// Persistent recurrence on mma.sync (bf16x3):
//   h_t = tanh(g_A[t] + h_{t-1} @ W_h^T)
// 128 CTAs x 256 thr; CTA tile 32(M) x 64(N); warps 2(M) x 4(N).
// W_h hi tile (64 x 1024 bf16 = 128 KB) RESIDENT in smem, loaded once.
// Streams per chunk (BK=32): Ah (2KB), Al (2KB), Bl (4KB), double-buffered.
// ---------------------------------------------------------------------------
#define BH_ROWB   2064                       // 2048 data + 16 pad (conflict-free)
#define R_OFF_BH  0
#define R_BH_SZ   (64 * BH_ROWB)             // 132096
#define R_A_SZ    (32 * ROWB)                // 2560
#define R_BL_SZ   (64 * ROWB)                // 5120
#define R_STG     (2 * R_A_SZ + R_BL_SZ)     // 10240  (Ah | Al | Bl)
#define R_OFF_STG R_BH_SZ
#define R_SMEM    (R_BH_SZ + 2 * R_STG)      // 152576

__global__ void __launch_bounds__(256, 1)
rnn_recur()
{
    extern __shared__ char smem[];
    const uint32_t sb = smem_to_u32(smem);
    const int tid = threadIdx.x, lane = tid & 31, wid = tid >> 5;
    const int wm = wid & 1, wn = wid >> 1;       // 2 x 4 warp grid
    const int bm = (blockIdx.x >> 4) * 32;       // 8 M-tiles
    const int bn = (blockIdx.x & 15) * 64;       // 16 N-tiles

    const uint32_t a_rb  = (uint32_t)(lane & 15) * ROWB + (uint32_t)(lane >> 4) * 16;
    const uint32_t bl_rb = (uint32_t)(lane & 7) * ROWB + (uint32_t)((lane >> 3) & 1) * 16;
    const uint32_t bh_rb = (uint32_t)(lane & 7) * BH_ROWB + (uint32_t)((lane >> 3) & 1) * 16;

    // ---- Load resident W_h hi tile: 64 rows x 1024 bf16 (8192 x 16B units)
    for (int u = tid; u < 8192; u += 256) {
        int row = u >> 7, seg = u & 127;
        cp16(sb + R_OFF_BH + row * BH_ROWB + seg * 16,
             g_Wih_h + (size_t)(bn + row) * WROW + INF + seg * 8);
    }
    CP_COMMIT();

    unsigned lgen = *(volatile unsigned*)&g_gen;

    for (int t = 0; t < T_STEPS; t++) {
        const __nv_bfloat16* hh = (t == 0) ? g_h0h : (g_Hh + (size_t)(t - 1) * BH);
        const __nv_bfloat16* hl = (t == 0) ? g_h0l : (g_Hl + (size_t)(t - 1) * BH);

        float c[2][4];
#pragma unroll
        for (int n = 0; n < 2; n++)
#pragma unroll
            for (int j = 0; j < 4; j++) c[n][j] = 0.0f;

        auto load_chunk = [&](int kc, int stage) {
            uint32_t base = sb + R_OFF_STG + stage * R_STG;
            // A hi/lo: 128 units each; threads 0-127 -> Ah, 128-255 -> Al
            {
                int u = tid & 127;
                int row = u >> 2, seg = u & 3;
                uint32_t so = row * ROWB + seg * 16;
                size_t g = (size_t)(bm + row) * HIDDEN + kc + seg * 8;
                if (tid < 128) cp16(base + so, hh + g);
                else           cp16(base + R_A_SZ + so, hl + g);
            }
            // B lo chunk: 64 rows x 4 segs = 256 units
            {
                int row = tid >> 2, seg = tid & 3;
                cp16(base + 2 * R_A_SZ + row * ROWB + seg * 16,
                     g_Wih_l + (size_t)(bn + row) * WROW + INF + kc + seg * 8);
            }
        };

        load_chunk(0, 0);
        CP_COMMIT();

        for (int ch = 0; ch < HIDDEN / 32; ch++) {
            if (ch + 1 < HIDDEN / 32) {
                load_chunk((ch + 1) << 5, (ch + 1) & 1);
                CP_COMMIT();
                CP_WAIT(1);
            } else {
                CP_WAIT(0);
            }
            __syncthreads();

            const uint32_t base = sb + R_OFF_STG + (ch & 1) * R_STG;
            const uint32_t kres = (uint32_t)(ch << 6);   // byte offset into resident rows
#pragma unroll
            for (int k16 = 0; k16 < 2; k16++) {
                const uint32_t kb = k16 * 32;
                uint32_t ah[4], al[4], bh[2][2], bl[2][2];
                uint32_t ra = base + (uint32_t)(wm * 16) * ROWB + kb + a_rb;
                LDSM4(ah[0], ah[1], ah[2], ah[3], ra);
                LDSM4(al[0], al[1], al[2], al[3], ra + R_A_SZ);
#pragma unroll
                for (int n = 0; n < 2; n++) {
                    uint32_t rres = sb + R_OFF_BH + (uint32_t)(wn * 16 + n * 8) * BH_ROWB
                                    + kres + kb + bh_rb;
                    LDSM2(bh[n][0], bh[n][1], rres);
                    uint32_t rbl = base + 2 * R_A_SZ + (uint32_t)(wn * 16 + n * 8) * ROWB
                                   + kb + bl_rb;
                    LDSM2(bl[n][0], bl[n][1], rbl);
                }
#pragma unroll
                for (int n = 0; n < 2; n++) {
                    mma_bf16(c[n], ah, bh[n]);
                    mma_bf16(c[n], al, bh[n]);
                    mma_bf16(c[n], ah, bl[n]);
                }
            }
            __syncthreads();
        }

        // Epilogue: tanh(acc + pre), split to bf16 hi/lo
        {
            const size_t ob = (size_t)t * BH;
            int r0 = bm + wm * 16 + (lane >> 2);
            int r1 = r0 + 8;
#pragma unroll
            for (int n = 0; n < 2; n++) {
                int col = bn + wn * 16 + n * 8 + (lane & 3) * 2;
                float2 p0 = *(const float2*)(g_A + ob + (size_t)r0 * HIDDEN + col);
                float2 p1 = *(const float2*)(g_A + ob + (size_t)r1 * HIDDEN + col);
                float h00 = tanhf(c[n][0] + p0.x);
                float h01 = tanhf(c[n][1] + p0.y);
                float h10 = tanhf(c[n][2] + p1.x);
                float h11 = tanhf(c[n][3] + p1.y);

                __nv_bfloat16 hb, lb;
                __nv_bfloat162 th, tl;
                split1(h00, hb, lb); th.x = hb; tl.x = lb;
                split1(h01, hb, lb); th.y = hb; tl.y = lb;
                *(__nv_bfloat162*)(g_Hh + ob + (size_t)r0 * HIDDEN + col) = th;
                *(__nv_bfloat162*)(g_Hl + ob + (size_t)r0 * HIDDEN + col) = tl;
                split1(h10, hb, lb); th.x = hb; tl.x = lb;
                split1(h11, hb, lb); th.y = hb; tl.y = lb;
                *(__nv_bfloat162*)(g_Hh + ob + (size_t)r1 * HIDDEN + col) = th;
                *(__nv_bfloat162*)(g_Hl + ob + (size_t)r1 * HIDDEN + col) = tl;

                if (t == T_STEPS - 1) {
                    float2 f0 = { h00, h01 }, f1 = { h10, h11 };
                    *(float2*)(g_Hlast + (size_t)r0 * HIDDEN + col) = f0;
                    *(float2*)(g_Hlast + (size_t)r1 * HIDDEN + col) = f1;
                }
            }
        }

        grid_bar(lgen);
    }
}

// ---------------------------------------------------------------------------
// In-place softmax over rows of 512 floats
// ---------------------------------------------------------------------------
__global__ void softmax512(float* __restrict__ O)
{
    __shared__ float red[4];
    long row = blockIdx.x;
    float4* p = (float4*)(O + row * (long)NCLS);
    float4 v = p[threadIdx.x];

    float m = fmaxf(fmaxf(v.x, v.y), fmaxf(v.z, v.w));
#pragma unroll
    for (int o = 16; o > 0; o >>= 1)
        m = fmaxf(m, __shfl_xor_sync(0xffffffffu, m, o));
    int warp = threadIdx.x >> 5;
    if ((threadIdx.x & 31) == 0) red[warp] = m;
    __syncthreads();
    m = fmaxf(fmaxf(red[0], red[1]), fmaxf(red[2], red[3]));

    float4 e;
    e.x = __expf(v.x - m);
    e.y = __expf(v.y - m);
    e.z = __expf(v.z - m);
    e.w = __expf(v.w - m);
    float s = e.x + e.y + e.z + e.w;
#pragma unroll
    for (int o = 16; o > 0; o >>= 1)
        s += __shfl_xor_sync(0xffffffffu, s, o);
    __syncthreads();
    if ((threadIdx.x & 31) == 0) red[warp] = s;
    __syncthreads();
    s = red[0] + red[1] + red[2] + red[3];

    float inv = 1.0f / s;
    e.x *= inv; e.y *= inv; e.z *= inv; e.w *= inv;
    p[threadIdx.x] = e;
}

// ---------------------------------------------------------------------------
// Launch (9 graph nodes)
// ---------------------------------------------------------------------------
extern "C" void kernel_launch(void* const* d_in, const int* in_sizes, int n_in,
                              void* d_out, int out_size)
{
    const float* x    = (const float*)d_in[0];
    const float* h0   = (const float*)d_in[1];
    const float* W_ih = (const float*)d_in[2];
    const float* b_ih = (const float*)d_in[3];
    const float* W_ho = (const float*)d_in[4];
    const float* b_ho = (const float*)d_in[5];
    float*       out  = (float*)d_out;

    float *pA, *pHlast;
    __nv_bfloat16 *pXh, *pXl, *pHh, *pHl, *pWih_h, *pWih_l, *pWoh, *pWol, *ph0h, *ph0l;
    cudaGetSymbolAddress((void**)&pA,     g_A);
    cudaGetSymbolAddress((void**)&pHlast, g_Hlast);
    cudaGetSymbolAddress((void**)&pXh,    g_Xh);
    cudaGetSymbolAddress((void**)&pXl,    g_Xl);
    cudaGetSymbolAddress((void**)&pHh,    g_Hh);
    cudaGetSymbolAddress((void**)&pHl,    g_Hl);
    cudaGetSymbolAddress((void**)&pWih_h, g_Wih_h);
    cudaGetSymbolAddress((void**)&pWih_l, g_Wih_l);
    cudaGetSymbolAddress((void**)&pWoh,   g_Who_h);
    cudaGetSymbolAddress((void**)&pWol,   g_Who_l);
    cudaGetSymbolAddress((void**)&ph0h,   g_h0h);
    cudaGetSymbolAddress((void**)&ph0l,   g_h0l);

    cudaFuncSetAttribute(gemm_mma_x3,
                         cudaFuncAttributeMaxDynamicSharedMemorySize, G_SMEM);
    cudaFuncSetAttribute(rnn_recur,
                         cudaFuncAttributeMaxDynamicSharedMemorySize, R_SMEM);

    // Splits: X, W_ih (full), W_ho, h0
    split_mat<<<4096, 256>>>(x,    INF,    TB,     INF,    pXh,    pXl);
    split_mat<<<512,  256>>>(W_ih, WROW,   HIDDEN, WROW,   pWih_h, pWih_l);
    split_mat<<<256,  256>>>(W_ho, HIDDEN, NCLS,   HIDDEN, pWoh,   pWol);
    split_mat<<<128,  256>>>(h0,   HIDDEN, BATCH,  HIDDEN, ph0h,   ph0l);

    // Phase 1: g_A = X @ Wx^T + b_ih
    {
        dim3 grid(HIDDEN / 128, TB / 128);   // (8, 1024)
        gemm_mma_x3<<<grid, 256, G_SMEM>>>(pXh, pXl, INF,
                                           pWih_h, pWih_l, WROW,
                                           b_ih, pA, HIDDEN, INF);
    }

    // Phase 2: persistent recurrence (mma.sync bf16x3, resident W hi)
    rnn_recur<<<NCTAS, 256, R_SMEM>>>();

    // Phase 3: out = H @ W_ho^T + b_ho, then in-place softmax
    {
        dim3 grid(NCLS / 128, TB / 128);     // (4, 1024)
        gemm_mma_x3<<<grid, 256, G_SMEM>>>(pHh, pHl, HIDDEN,
                                           pWoh, pWol, HIDDEN,
                                           b_ho, out, NCLS, HIDDEN);
        softmax512<<<TB, 128>>>(out);
    }

    // h_last
    cudaMemcpyAsync(out + (long)TB * NCLS, pHlast,
                    (size_t)BH * sizeof(float), cudaMemcpyDeviceToDevice);
}